// round 2
// baseline (speedup 1.0000x reference)
#include <cuda_runtime.h>
#include <mma.h>
#include <cstdint>

using namespace nvcuda;

#define HIDDEN 4096
#define NBLK 8
#define BLK 512
#define TILE_M 128
#define TILE_N 128
#define TILE_K 32
#define NCHUNK 16           // 512 / 32
#define THREADS 256

// smem: 2 stages of (A 128x32 + B 32x128) fp32 = 64 KB
#define A_ELEMS (TILE_M * TILE_K)     // 4096
#define B_ELEMS (TILE_K * TILE_N)     // 4096
#define SM_A(st) (sm + (st) * A_ELEMS)
#define SM_B(st) (sm + 2 * A_ELEMS + (st) * B_ELEMS)
#define SMEM_BYTES ((2 * A_ELEMS + 2 * B_ELEMS) * 4)   // 65536

// pre-rounded (rna->tf32) copy of blocks, same [k][b][c] layout
__device__ float g_bt[NBLK * BLK * BLK];

__device__ __forceinline__ uint32_t smem_u32(const void* p) {
    uint32_t a;
    asm("{ .reg .u64 t; cvta.to.shared.u64 t, %1; cvt.u32.u64 %0, t; }" : "=r"(a) : "l"(p));
    return a;
}
__device__ __forceinline__ float f2tf32(float x) {
    uint32_t r; asm("cvt.rna.tf32.f32 %0, %1;" : "=r"(r) : "f"(x));
    return __uint_as_float(r);
}
#define CPA16(d, s)   asm volatile("cp.async.cg.shared.global [%0], [%1], 16;" :: "r"(d), "l"(s) : "memory")
#define CPA_COMMIT()  asm volatile("cp.async.commit_group;" ::: "memory")
#define CPA_WAIT(n)   asm volatile("cp.async.wait_group %0;" :: "n"(n) : "memory")

// ------------- pre-pass: round blocks to tf32 grid -------------
__global__ void round_blocks_k(const float* __restrict__ blocks) {
    int i = (blockIdx.x * blockDim.x + threadIdx.x) * 4;
    float4 v = *(const float4*)(blocks + i);
    float4 o = { f2tf32(v.x), f2tf32(v.y), f2tf32(v.z), f2tf32(v.w) };
    *(float4*)(g_bt + i) = o;
}

// ------------- grouped GEMM -------------
// out[m, k*512 + c] = sum_b x[m, k*512 + b] * blocks[k][b][c]
// grid.x = 32 (k*4 + ntile)  [inner -> schedule-adjacent CTAs share x slice]
// grid.y = tokens/128
__global__ __launch_bounds__(THREADS, 2)
void grouped_gemm(const float* __restrict__ x, float* __restrict__ out) {
    extern __shared__ float sm[];
    int tid = threadIdx.x;
    int wid = tid >> 5;
    int wm = wid >> 2;           // 0..1  (m direction, 64 rows each)
    int wn = wid & 3;            // 0..3  (n direction, 32 cols each)

    int k  = blockIdx.x >> 2;
    int nt = blockIdx.x & 3;
    int m0 = blockIdx.y * TILE_M;
    int n0 = nt * TILE_N;

    const float* xk = x + (size_t)m0 * HIDDEN + k * BLK;
    const float* bt = g_bt + (size_t)k * BLK * BLK + n0;

    wmma::fragment<wmma::accumulator, 16, 16, 8, float> c[4][2];
#pragma unroll
    for (int im = 0; im < 4; im++)
#pragma unroll
        for (int in = 0; in < 2; in++)
            wmma::fill_fragment(c[im][in], 0.0f);

    // ---- prologue: chunk 0 into stage 0 ----
    {
#pragma unroll
        for (int j = 0; j < 4; j++) {               // A: 1024 float4
            int idx = j * THREADS + tid;
            int row = idx >> 3, q = idx & 7;
            float4 v = *(const float4*)(xk + (size_t)row * HIDDEN + q * 4);
            float4 o = { f2tf32(v.x), f2tf32(v.y), f2tf32(v.z), f2tf32(v.w) };
            *(float4*)(SM_A(0) + row * TILE_K + q * 4) = o;
        }
#pragma unroll
        for (int j = 0; j < 4; j++) {               // B: 1024 float4 via cp.async
            int idx = j * THREADS + tid;
            int row = idx >> 5, c4 = idx & 31;
            uint32_t dst = smem_u32(SM_B(0) + row * TILE_N + c4 * 4);
            CPA16(dst, bt + (size_t)row * BLK + c4 * 4);
        }
        CPA_COMMIT();
    }

    for (int i = 0; i < NCHUNK; i++) {
        int cur = i & 1;
        // issue loads for chunk i+1 into the other stage
        if (i + 1 < NCHUNK) {
            int nb = cur ^ 1;
#pragma unroll
            for (int j = 0; j < 4; j++) {
                int idx = j * THREADS + tid;
                int row = idx >> 3, q = idx & 7;
                float4 v = *(const float4*)(xk + (size_t)row * HIDDEN + (i + 1) * TILE_K + q * 4);
                float4 o = { f2tf32(v.x), f2tf32(v.y), f2tf32(v.z), f2tf32(v.w) };
                *(float4*)(SM_A(nb) + row * TILE_K + q * 4) = o;
            }
#pragma unroll
            for (int j = 0; j < 4; j++) {
                int idx = j * THREADS + tid;
                int row = idx >> 5, c4 = idx & 31;
                uint32_t dst = smem_u32(SM_B(nb) + row * TILE_N + c4 * 4);
                CPA16(dst, bt + (size_t)row * BLK + (size_t)(i + 1) * TILE_K * BLK + c4 * 4);
            }
            CPA_COMMIT();
            CPA_WAIT(1);      // chunk i's B resident
        } else {
            CPA_WAIT(0);
        }
        __syncthreads();

        // ---- compute chunk i ----
        const float* Abase = SM_A(cur) + wm * 64 * TILE_K;
        const float* Bbase = SM_B(cur) + wn * 32;
#pragma unroll
        for (int ks = 0; ks < 4; ks++) {
            wmma::fragment<wmma::matrix_a, 16, 16, 8, wmma::precision::tf32, wmma::row_major> a[4];
            wmma::fragment<wmma::matrix_b, 16, 16, 8, wmma::precision::tf32, wmma::row_major> b[2];
#pragma unroll
            for (int im = 0; im < 4; im++)
                wmma::load_matrix_sync(a[im], Abase + im * 16 * TILE_K + ks * 8, TILE_K);
#pragma unroll
            for (int in = 0; in < 2; in++)
                wmma::load_matrix_sync(b[in], Bbase + ks * 8 * TILE_N + in * 16, TILE_N);
#pragma unroll
            for (int im = 0; im < 4; im++)
#pragma unroll
                for (int in = 0; in < 2; in++)
                    wmma::mma_sync(c[im][in], a[im], b[in], c[im][in]);
        }
        __syncthreads();   // protect stages before next iteration overwrites
    }

    // ---- epilogue: direct global stores ----
    float* obase = out + (size_t)(m0 + wm * 64) * HIDDEN + k * BLK + n0 + wn * 32;
#pragma unroll
    for (int im = 0; im < 4; im++)
#pragma unroll
        for (int in = 0; in < 2; in++)
            wmma::store_matrix_sync(obase + (size_t)im * 16 * HIDDEN + in * 16,
                                    c[im][in], HIDDEN, wmma::mem_row_major);
}

extern "C" void kernel_launch(void* const* d_in, const int* in_sizes, int n_in,
                              void* d_out, int out_size) {
    const float* x = (const float*)d_in[0];
    const float* blocks = (const float*)d_in[1];
    float* out = (float*)d_out;
    int tokens = in_sizes[0] / HIDDEN;   // 16384

    int belem = NBLK * BLK * BLK;        // 2M elements
    round_blocks_k<<<belem / (256 * 4), 256>>>(blocks);

    static int smem_set = 0;
    cudaFuncSetAttribute(grouped_gemm, cudaFuncAttributeMaxDynamicSharedMemorySize, SMEM_BYTES);
    (void)smem_set;

    grouped_gemm<<<dim3(NBLK * (BLK / TILE_N), tokens / TILE_M), THREADS, SMEM_BYTES>>>(x, out);
}

// round 3
// speedup vs baseline: 3.7007x; 3.7007x over previous
#include <cuda_runtime.h>
#include <cstdint>

#define HIDDEN 4096
#define NBLK 8
#define BLK 512
#define TILE_M 128
#define TILE_N 128
#define TILE_K 32
#define NCHUNK 16
#define THREADS 128

// smem: A stages [0,4096),[4096,8192)  B stages [8192,12288),[12288,16384) floats
#define SMEM_FLOATS 16384
#define SMEM_BYTES (SMEM_FLOATS * 4)
#define B_SM_OFF 8192

// B pre-packed into mma-fragment order:
// word(kb,nt,chunk,nb,ks,lane,reg) = kb*262144 + nt*65536 + chunk*4096 + nb*256 + ks*64 + lane*2 + reg
__device__ float g_bf[NBLK * BLK * BLK];

__device__ __forceinline__ float f2tf32(float x) {
    uint32_t r; asm("cvt.rna.tf32.f32 %0, %1;" : "=r"(r) : "f"(x));
    return __uint_as_float(r);
}
__device__ __forceinline__ uint32_t smem_u32(const void* p) {
    uint32_t a;
    asm("{ .reg .u64 t; cvta.to.shared.u64 t, %1; cvt.u32.u64 %0, t; }" : "=r"(a) : "l"(p));
    return a;
}
#define CPA16(d, s)   asm volatile("cp.async.cg.shared.global [%0], [%1], 16;" :: "r"(d), "l"(s) : "memory")
#define CPA_COMMIT()  asm volatile("cp.async.commit_group;" ::: "memory")
#define CPA_WAIT(n)   asm volatile("cp.async.wait_group %0;" :: "n"(n) : "memory")

__device__ __forceinline__ void mma8(float* c, const uint32_t* a, const uint32_t* b) {
    asm volatile(
        "mma.sync.aligned.m16n8k8.row.col.f32.tf32.tf32.f32 "
        "{%0,%1,%2,%3}, {%4,%5,%6,%7}, {%8,%9}, {%0,%1,%2,%3};"
        : "+f"(c[0]), "+f"(c[1]), "+f"(c[2]), "+f"(c[3])
        : "r"(a[0]), "r"(a[1]), "r"(a[2]), "r"(a[3]), "r"(b[0]), "r"(b[1]));
}

// ---------- pre-pass: blocks -> tf32-rounded, fragment-order g_bf ----------
__global__ void pack_b_k(const float* __restrict__ blocks) {
    int w = blockIdx.x * blockDim.x + threadIdx.x;      // 0 .. 2M-1
    int kb    = w >> 18;
    int r     = w & 0x3FFFF;
    int reg   = r & 1;
    int lane  = (r >> 1) & 31;
    int ks    = (r >> 6) & 3;
    int nb    = (r >> 8) & 15;
    int chunk = (r >> 12) & 15;
    int nt    = r >> 16;
    int kc8 = (lane & 3) + (reg << 2);      // k within 8
    int b   = chunk * 32 + ks * 8 + kc8;    // K dim of block
    int c   = nt * 128 + nb * 8 + (lane >> 2);  // N dim
    g_bf[w] = f2tf32(blocks[(size_t)kb * BLK * BLK + (size_t)b * BLK + c]);
}

// ---------- grouped GEMM ----------
// out[m, kb*512 + c] = sum_b x[m, kb*512 + b] * blocks[kb][b][c]
__global__ __launch_bounds__(THREADS, 2)
void grouped_gemm(const float* __restrict__ x, float* __restrict__ out) {
    extern __shared__ float sm[];
    const int tid  = threadIdx.x;
    const int wid  = tid >> 5;
    const int lane = tid & 31;
    const int wm = wid >> 1;         // 0..1, 64 rows
    const int wn = wid & 1;          // 0..1, 64 cols

    const int kb = blockIdx.x >> 2;
    const int nt = blockIdx.x & 3;
    const int m0 = blockIdx.y * TILE_M;

    const float* xk = x + (size_t)m0 * HIDDEN + kb * BLK;
    const float* bf = g_bf + (size_t)kb * 262144 + nt * 65536;

    // A-writer per-thread constants (warp covers 4 rows x 8 k-float4s per pass, 8 passes)
    const int qw  = lane & 7;            // float4 index along K
    const int mi  = lane >> 3;           // row within warp group
    const int ksw = qw >> 1;
    const int sigma = (qw & 3) | (qw & 4) | ((qw & 4) << 2);
    const int regw  = (wid >> 1) | ((qw & 1) << 1);
    const int F0    = ((wid & 1) << 4) | (mi << 2);
    const int wconst = regw * 128 + ksw * 32;
    const float* arow = xk + (size_t)(wid * 4 + mi) * HIDDEN + qw * 4;  // + p*16*HIDDEN + chunk*32

    float acc[4][8][4];
#pragma unroll
    for (int im = 0; im < 4; im++)
#pragma unroll
        for (int jn = 0; jn < 8; jn++)
#pragma unroll
            for (int r = 0; r < 4; r++) acc[im][jn][r] = 0.0f;

    float4 pf[8];

#define LOAD_PF(ci) do { \
    _Pragma("unroll") \
    for (int p = 0; p < 8; p++) \
        pf[p] = *(const float4*)(arow + (size_t)p * 16 * HIDDEN + (ci) * TILE_K); \
} while (0)

#define STS_A(st) do { \
    float* as_ = sm + (st) * 4096 + wconst; \
    _Pragma("unroll") \
    for (int p = 0; p < 8; p++) { \
        float* ap = as_ + p * 512; \
        ap[(F0 + 0) ^ sigma] = f2tf32(pf[p].x); \
        ap[(F0 + 1) ^ sigma] = f2tf32(pf[p].y); \
        ap[(F0 + 2) ^ sigma] = f2tf32(pf[p].z); \
        ap[(F0 + 3) ^ sigma] = f2tf32(pf[p].w); \
    } \
} while (0)

#define CPB(ci, st) do { \
    uint32_t dst_ = smem_u32(sm + B_SM_OFF + (st) * 4096) + tid * 16; \
    const float* src_ = bf + (ci) * 4096 + tid * 4; \
    _Pragma("unroll") \
    for (int j = 0; j < 8; j++) CPA16(dst_ + j * 2048, src_ + j * 512); \
} while (0)

    // ---- prologue ----
    LOAD_PF(0);
    STS_A(0);
    CPB(0, 0);
    CPA_COMMIT();
    LOAD_PF(1);

#pragma unroll 1
    for (int i = 0; i < NCHUNK; i++) {
        const int cur = i & 1;
        if (i < NCHUNK - 1) {
            STS_A(cur ^ 1);
            CPB(i + 1, cur ^ 1);
            CPA_COMMIT();
            if (i < NCHUNK - 2) LOAD_PF(i + 2);
            CPA_WAIT(1);
        } else {
            CPA_WAIT(0);
        }
        __syncthreads();

        const float* As = sm + cur * 4096;
        const float* Bs = sm + B_SM_OFF + cur * 4096;
#pragma unroll
        for (int ks = 0; ks < 4; ks++) {
            uint32_t a[4][4];
#pragma unroll
            for (int im = 0; im < 4; im++) {
                const int rbg = wm * 4 + im;
#pragma unroll
                for (int r = 0; r < 4; r++) {
                    const int qa = (r >> 1) | (ks << 1);
                    const int sg = (qa & 3) | (qa & 4) | ((qa & 4) << 2);
                    a[im][r] = __float_as_uint(As[rbg * 512 + r * 128 + ks * 32 + (lane ^ sg)]);
                }
            }
            uint32_t b[8][2];
#pragma unroll
            for (int jn = 0; jn < 8; jn++) {
                const int nb = wn * 8 + jn;
                float2 bb = *(const float2*)(Bs + nb * 256 + ks * 64 + lane * 2);
                b[jn][0] = __float_as_uint(bb.x);
                b[jn][1] = __float_as_uint(bb.y);
            }
#pragma unroll
            for (int im = 0; im < 4; im++)
#pragma unroll
                for (int jn = 0; jn < 8; jn++)
                    mma8(acc[im][jn], a[im], b[jn]);
        }
        __syncthreads();
    }

    // ---- epilogue: direct vectorized stores ----
    const int gi = lane >> 2, ti = lane & 3;
    float* ob = out + (size_t)(m0 + wm * 64 + gi) * HIDDEN + kb * BLK + nt * 128 + wn * 64 + ti * 2;
#pragma unroll
    for (int im = 0; im < 4; im++) {
#pragma unroll
        for (int jn = 0; jn < 8; jn++) {
            float2 v0 = { acc[im][jn][0], acc[im][jn][1] };
            float2 v1 = { acc[im][jn][2], acc[im][jn][3] };
            *(float2*)(ob + (size_t)(im * 16) * HIDDEN + jn * 8)     = v0;
            *(float2*)(ob + (size_t)(im * 16 + 8) * HIDDEN + jn * 8) = v1;
        }
    }
}

extern "C" void kernel_launch(void* const* d_in, const int* in_sizes, int n_in,
                              void* d_out, int out_size) {
    const float* x = (const float*)d_in[0];
    const float* blocks = (const float*)d_in[1];
    float* out = (float*)d_out;
    int tokens = in_sizes[0] / HIDDEN;   // 16384

    pack_b_k<<<(NBLK * BLK * BLK) / 256, 256>>>(blocks);

    cudaFuncSetAttribute(grouped_gemm, cudaFuncAttributeMaxDynamicSharedMemorySize, SMEM_BYTES);
    grouped_gemm<<<dim3(NBLK * (BLK / TILE_N), tokens / TILE_M), THREADS, SMEM_BYTES>>>(x, out);
}